// round 15
// baseline (speedup 1.0000x reference)
#include <cuda_runtime.h>
#include <cstdint>

#define Bb 8
#define Tt 96
#define Ss 192
#define Dd 512
#define ROWS (Bb*Tt)      // 768
#define UROWS (Bb*Ss)     // 1536
#define NT (Dd/16)        // 32 k-tiles

// Scratch
__device__ float g_wq[ROWS * Dd];        // inputs @ Wq^T                 [768,512]
__device__ float g_uh[UROWS * Dd];       // mems @ Wc^T + bc              [1536,512]
__device__ float g_part[ROWS * Dd];      // inputs @ Wout[:,512:]^T + bout[768,512]
__device__ float g_c[ROWS * Dd];         // context                       [768,512]

#define NEG_INF (-__int_as_float(0x7f800000))

__device__ __forceinline__ float tanh_ap(float x) {
    float y;
    asm("tanh.approx.f32 %0, %1;" : "=f"(y) : "f"(x));
    return y;
}
__device__ __forceinline__ unsigned long long ffma2(unsigned long long a,
                                                    unsigned long long b,
                                                    unsigned long long c) {
    unsigned long long d;
    asm("fma.rn.f32x2 %0, %1, %2, %3;" : "=l"(d) : "l"(a), "l"(b), "l"(c));
    return d;
}
__device__ __forceinline__ float2 unpk(unsigned long long p) {
    float lo, hi;
    asm("mov.b64 {%0, %1}, %2;" : "=f"(lo), "=f"(hi) : "l"(p));
    return make_float2(lo, hi);
}

// ---------------------------------------------------------------------------
// Pipelined f32x2 GEMM body (identical math to R5 passing kernel).
// Double-buffered smem, W pre-duplicated as f32x2 pairs, float4 epilogue.
// ---------------------------------------------------------------------------
template <int BM>
__device__ __forceinline__ void gemm_body(
    float (*As)[BM + 4],            // [32][BM+4]  (2 buffers x 16 k-rows)
    float (*Ws2)[136],              // [32][136]
    const float* __restrict__ A, int lda,
    const float* __restrict__ W, int ldw,
    const float* __restrict__ bias,
    const float* __restrict__ part,
    float* __restrict__ C,
    int bm, int bn)
{
    constexpr int MT = BM / 16;    // 8 or 4
    constexpr int P  = MT / 2;     // 4 or 2

    const int tid = threadIdx.x;
    const int tx = tid & 15;
    const int ty = tid >> 4;
    const int lr = tid >> 2;         // 0..63
    const int lk = (tid & 3) * 4;    // 0,4,8,12

    const float* Ap0 = A + (size_t)(bm + lr) * lda + lk;
    const float* Ap1 = A + (size_t)(bm + lr + 64) * lda + lk;   // BM==128 only
    const float* Wp  = W + (size_t)(bn + lr) * ldw + lk;

    unsigned long long acc[P][4];
#pragma unroll
    for (int p = 0; p < P; p++)
#pragma unroll
        for (int j = 0; j < 4; j++) acc[p][j] = 0ull;

    float4 a0, a1, wv;

    a0 = *reinterpret_cast<const float4*>(Ap0);
    if (BM == 128) a1 = *reinterpret_cast<const float4*>(Ap1);
    wv = *reinterpret_cast<const float4*>(Wp);
    {
        const int kb = 0;
        As[kb + lk + 0][lr] = a0.x; As[kb + lk + 1][lr] = a0.y;
        As[kb + lk + 2][lr] = a0.z; As[kb + lk + 3][lr] = a0.w;
        if (BM == 128) {
            As[kb + lk + 0][lr + 64] = a1.x; As[kb + lk + 1][lr + 64] = a1.y;
            As[kb + lk + 2][lr + 64] = a1.z; As[kb + lk + 3][lr + 64] = a1.w;
        }
        *reinterpret_cast<float2*>(&Ws2[kb + lk + 0][2 * lr]) = make_float2(wv.x, wv.x);
        *reinterpret_cast<float2*>(&Ws2[kb + lk + 1][2 * lr]) = make_float2(wv.y, wv.y);
        *reinterpret_cast<float2*>(&Ws2[kb + lk + 2][2 * lr]) = make_float2(wv.z, wv.z);
        *reinterpret_cast<float2*>(&Ws2[kb + lk + 3][2 * lr]) = make_float2(wv.w, wv.w);
    }
    __syncthreads();

#pragma unroll 1
    for (int t = 0; t < NT; ++t) {
        if (t + 1 < NT) {
            const int off = (t + 1) * 16;
            a0 = *reinterpret_cast<const float4*>(Ap0 + off);
            if (BM == 128) a1 = *reinterpret_cast<const float4*>(Ap1 + off);
            wv = *reinterpret_cast<const float4*>(Wp + off);
        }

        const int kb = (t & 1) * 16;
#pragma unroll
        for (int k = 0; k < 16; k++) {
            const float* ar = &As[kb + k][ty * MT];
            unsigned long long ap[P];
#pragma unroll
            for (int p = 0; p < P; p++)
                ap[p] = *reinterpret_cast<const unsigned long long*>(ar + 2 * p);
            const float* wr = &Ws2[kb + k][tx * 8];
            unsigned long long wd[4];
#pragma unroll
            for (int j = 0; j < 4; j++)
                wd[j] = *reinterpret_cast<const unsigned long long*>(wr + 2 * j);
#pragma unroll
            for (int p = 0; p < P; p++)
#pragma unroll
                for (int j = 0; j < 4; j++)
                    acc[p][j] = ffma2(ap[p], wd[j], acc[p][j]);
        }

        if (t + 1 < NT) {
            const int kb2 = ((t + 1) & 1) * 16;
            As[kb2 + lk + 0][lr] = a0.x; As[kb2 + lk + 1][lr] = a0.y;
            As[kb2 + lk + 2][lr] = a0.z; As[kb2 + lk + 3][lr] = a0.w;
            if (BM == 128) {
                As[kb2 + lk + 0][lr + 64] = a1.x; As[kb2 + lk + 1][lr + 64] = a1.y;
                As[kb2 + lk + 2][lr + 64] = a1.z; As[kb2 + lk + 3][lr + 64] = a1.w;
            }
            *reinterpret_cast<float2*>(&Ws2[kb2 + lk + 0][2 * lr]) = make_float2(wv.x, wv.x);
            *reinterpret_cast<float2*>(&Ws2[kb2 + lk + 1][2 * lr]) = make_float2(wv.y, wv.y);
            *reinterpret_cast<float2*>(&Ws2[kb2 + lk + 2][2 * lr]) = make_float2(wv.z, wv.z);
            *reinterpret_cast<float2*>(&Ws2[kb2 + lk + 3][2 * lr]) = make_float2(wv.w, wv.w);
        }
        __syncthreads();
    }

    const int n0 = bn + tx * 4;
    float4 bv4 = make_float4(0.f, 0.f, 0.f, 0.f);
    if (bias) bv4 = *reinterpret_cast<const float4*>(bias + n0);
#pragma unroll
    for (int p = 0; p < P; p++) {
        const int m = bm + ty * MT + 2 * p;
        float2 v0 = unpk(acc[p][0]);
        float2 v1 = unpk(acc[p][1]);
        float2 v2 = unpk(acc[p][2]);
        float2 v3 = unpk(acc[p][3]);
        float4 r0 = make_float4(v0.x + bv4.x, v1.x + bv4.y, v2.x + bv4.z, v3.x + bv4.w);
        float4 r1 = make_float4(v0.y + bv4.x, v1.y + bv4.y, v2.y + bv4.z, v3.y + bv4.w);
        if (part) {
            float4 p0 = *reinterpret_cast<const float4*>(part + (size_t)m * Dd + n0);
            float4 p1 = *reinterpret_cast<const float4*>(part + (size_t)(m + 1) * Dd + n0);
            r0.x += p0.x; r0.y += p0.y; r0.z += p0.z; r0.w += p0.w;
            r1.x += p1.x; r1.y += p1.y; r1.z += p1.z; r1.w += p1.w;
        }
        *reinterpret_cast<float4*>(C + (size_t)m * Dd + n0) = r0;
        *reinterpret_cast<float4*>(C + (size_t)(m + 1) * Dd + n0) = r1;
    }
}

// ---------------------------------------------------------------------------
__global__ __launch_bounds__(256) void mega_gemm1(
    const float* __restrict__ inputs, const float* __restrict__ mems,
    const float* __restrict__ Wq, const float* __restrict__ Wc,
    const float* __restrict__ bc, const float* __restrict__ Wout,
    const float* __restrict__ bout)
{
    __shared__ float As[32][132];
    __shared__ float Ws2[32][136];
    const int bx = blockIdx.x;
    if (bx < 48) {
        gemm_body<128>(As, Ws2, inputs, Dd, Wq, Dd, nullptr, nullptr, g_wq,
                       (bx >> 3) * 128, (bx & 7) * 64);
    } else if (bx < 144) {
        const int t = bx - 48;
        gemm_body<128>(As, Ws2, mems, Dd, Wc, Dd, bc, nullptr, g_uh,
                       (t >> 3) * 128, (t & 7) * 64);
    } else {
        const int t = bx - 144;
        gemm_body<128>(As, Ws2, inputs, Dd, Wout + Dd, 2 * Dd, bout, nullptr, g_part,
                       (t >> 3) * 128, (t & 7) * 64);
    }
}

__global__ __launch_bounds__(256) void gemm2(const float* __restrict__ Wout,
                                             float* __restrict__ out_attn)
{
    __shared__ float As[32][68];
    __shared__ float Ws2[32][136];
    gemm_body<64>(As, Ws2, g_c, Dd, Wout, 2 * Dd, nullptr, g_part, out_attn,
                  (blockIdx.x >> 3) * 64, (blockIdx.x & 7) * 64);
}

// ---------------------------------------------------------------------------
// Batched attention: 4 t-rows per block.  Grid = Bb * Tt/4 = 192 blocks.
// uh and mems tiles are loaded once per block and reused across 4 rows.
// ---------------------------------------------------------------------------
__global__ __launch_bounds__(256) void attn_fused4(
    const float* __restrict__ mems, const int* __restrict__ mem_masks,
    const float* __restrict__ v, float* __restrict__ out_align)
{
    __shared__ float sm_logit[4][200];
    __shared__ float smw[4][200];
    __shared__ float red[256];

    const int bg = blockIdx.x;        // 0..191
    const int b = bg / (Tt / 4);
    const int tg = bg % (Tt / 4);
    const int row0 = b * Tt + tg * 4;
    const int tid = threadIdx.x;
    const int warp = tid >> 5;
    const int lane = tid & 31;
    const int len = mem_masks[b];

    // Per-lane m-slice of v and wq for the 4 rows
    float4 vr[4], wqr[4][4];
#pragma unroll
    for (int j = 0; j < 4; j++)
        vr[j] = *reinterpret_cast<const float4*>(v + j * 128 + lane * 4);
#pragma unroll
    for (int r = 0; r < 4; r++) {
        const float* wqrow = g_wq + (size_t)(row0 + r) * Dd;
#pragma unroll
        for (int j = 0; j < 4; j++)
            wqr[r][j] = *reinterpret_cast<const float4*>(wqrow + j * 128 + lane * 4);
    }

    // Scores for 4 rows: warp handles s = it*8 + warp
#pragma unroll 1
    for (int it = 0; it < Ss / 8; it++) {
        const int s = it * 8 + warp;
        if (s < len) {
            const float* uhp = g_uh + (size_t)(b * Ss + s) * Dd;
            float acc[4] = {0.f, 0.f, 0.f, 0.f};
#pragma unroll
            for (int j = 0; j < 4; j++) {
                float4 u = *reinterpret_cast<const float4*>(uhp + j * 128 + lane * 4);
#pragma unroll
                for (int r = 0; r < 4; r++) {
                    acc[r] = fmaf(vr[j].x, tanh_ap(wqr[r][j].x + u.x), acc[r]);
                    acc[r] = fmaf(vr[j].y, tanh_ap(wqr[r][j].y + u.y), acc[r]);
                    acc[r] = fmaf(vr[j].z, tanh_ap(wqr[r][j].z + u.z), acc[r]);
                    acc[r] = fmaf(vr[j].w, tanh_ap(wqr[r][j].w + u.w), acc[r]);
                }
            }
#pragma unroll
            for (int r = 0; r < 4; r++)
#pragma unroll
                for (int o = 16; o; o >>= 1)
                    acc[r] += __shfl_xor_sync(0xFFFFFFFFu, acc[r], o);
            if (lane == 0) {
#pragma unroll
                for (int r = 0; r < 4; r++) sm_logit[r][s] = acc[r];
            }
        }
    }
    __syncthreads();

    // Masked softmax, one row at a time (all threads participate)
    const bool valid = (tid < Ss) && (tid < len);
#pragma unroll 1
    for (int r = 0; r < 4; r++) {
        float x = valid ? sm_logit[r][tid] : NEG_INF;
        red[tid] = x;
        __syncthreads();
#pragma unroll
        for (int s = 128; s > 0; s >>= 1) {
            if (tid < s) red[tid] = fmaxf(red[tid], red[tid + s]);
            __syncthreads();
        }
        const float mx = red[0];
        __syncthreads();

        const float e = valid ? __expf(x - mx) : 0.f;
        red[tid] = e;
        __syncthreads();
#pragma unroll
        for (int s = 128; s > 0; s >>= 1) {
            if (tid < s) red[tid] += red[tid + s];
            __syncthreads();
        }
        const float rsum = 1.f / red[0];

        if (tid < Ss) {
            const float w = e * rsum;
            smw[r][tid] = w;
            out_align[(size_t)(row0 + r) * Ss + tid] = w;
        }
        __syncthreads();
    }

    // Context for 4 rows: mems loads shared across rows.  Thread owns float2 of d.
    const int d0 = tid * 2;
    const float* mb = mems + (size_t)b * Ss * Dd + d0;
    float cx[4] = {0.f, 0.f, 0.f, 0.f};
    float cy[4] = {0.f, 0.f, 0.f, 0.f};
#pragma unroll 2
    for (int s = 0; s < Ss; s += 4) {
        float4 w0 = *reinterpret_cast<const float4*>(&smw[0][s]);
        float4 w1 = *reinterpret_cast<const float4*>(&smw[1][s]);
        float4 w2 = *reinterpret_cast<const float4*>(&smw[2][s]);
        float4 w3 = *reinterpret_cast<const float4*>(&smw[3][s]);
        float2 m0 = *reinterpret_cast<const float2*>(mb + (size_t)(s + 0) * Dd);
        float2 m1 = *reinterpret_cast<const float2*>(mb + (size_t)(s + 1) * Dd);
        float2 m2 = *reinterpret_cast<const float2*>(mb + (size_t)(s + 2) * Dd);
        float2 m3 = *reinterpret_cast<const float2*>(mb + (size_t)(s + 3) * Dd);
        cx[0] = fmaf(w0.x, m0.x, cx[0]); cy[0] = fmaf(w0.x, m0.y, cy[0]);
        cx[0] = fmaf(w0.y, m1.x, cx[0]); cy[0] = fmaf(w0.y, m1.y, cy[0]);
        cx[0] = fmaf(w0.z, m2.x, cx[0]); cy[0] = fmaf(w0.z, m2.y, cy[0]);
        cx[0] = fmaf(w0.w, m3.x, cx[0]); cy[0] = fmaf(w0.w, m3.y, cy[0]);
        cx[1] = fmaf(w1.x, m0.x, cx[1]); cy[1] = fmaf(w1.x, m0.y, cy[1]);
        cx[1] = fmaf(w1.y, m1.x, cx[1]); cy[1] = fmaf(w1.y, m1.y, cy[1]);
        cx[1] = fmaf(w1.z, m2.x, cx[1]); cy[1] = fmaf(w1.z, m2.y, cy[1]);
        cx[1] = fmaf(w1.w, m3.x, cx[1]); cy[1] = fmaf(w1.w, m3.y, cy[1]);
        cx[2] = fmaf(w2.x, m0.x, cx[2]); cy[2] = fmaf(w2.x, m0.y, cy[2]);
        cx[2] = fmaf(w2.y, m1.x, cx[2]); cy[2] = fmaf(w2.y, m1.y, cy[2]);
        cx[2] = fmaf(w2.z, m2.x, cx[2]); cy[2] = fmaf(w2.z, m2.y, cy[2]);
        cx[2] = fmaf(w2.w, m3.x, cx[2]); cy[2] = fmaf(w2.w, m3.y, cy[2]);
        cx[3] = fmaf(w3.x, m0.x, cx[3]); cy[3] = fmaf(w3.x, m0.y, cy[3]);
        cx[3] = fmaf(w3.y, m1.x, cx[3]); cy[3] = fmaf(w3.y, m1.y, cy[3]);
        cx[3] = fmaf(w3.z, m2.x, cx[3]); cy[3] = fmaf(w3.z, m2.y, cy[3]);
        cx[3] = fmaf(w3.w, m3.x, cx[3]); cy[3] = fmaf(w3.w, m3.y, cy[3]);
    }
#pragma unroll
    for (int r = 0; r < 4; r++) {
        float2 c2; c2.x = cx[r]; c2.y = cy[r];
        *reinterpret_cast<float2*>(g_c + (size_t)(row0 + r) * Dd + d0) = c2;
    }
}

// ---------------------------------------------------------------------------
extern "C" void kernel_launch(void* const* d_in, const int* in_sizes, int n_in,
                              void* d_out, int out_size) {
    const float* inputs    = (const float*)d_in[0];
    const float* mems      = (const float*)d_in[1];
    const int*   mem_masks = (const int*)d_in[2];
    const float* Wq        = (const float*)d_in[3];
    const float* Wc        = (const float*)d_in[4];
    const float* bc        = (const float*)d_in[5];
    const float* v         = (const float*)d_in[6];
    const float* Wout      = (const float*)d_in[7];
    const float* bout      = (const float*)d_in[8];

    float* out_attn  = (float*)d_out;               // [768,512]
    float* out_align = (float*)d_out + ROWS * Dd;   // [768,192]

    mega_gemm1<<<192, 256>>>(inputs, mems, Wq, Wc, bc, Wout, bout);
    attn_fused4<<<Bb * (Tt / 4), 256>>>(mems, mem_masks, v, out_align);
    gemm2<<<96, 256>>>(Wout, out_attn);
}

// round 16
// speedup vs baseline: 1.5083x; 1.5083x over previous
#include <cuda_runtime.h>
#include <cstdint>

#define Bb 8
#define Tt 96
#define Ss 192
#define Dd 512
#define ROWS (Bb*Tt)      // 768
#define UROWS (Bb*Ss)     // 1536

// Scratch
__device__ float g_wq[ROWS * Dd];        // inputs @ Wq^T                 [768,512]
__device__ float g_uh[UROWS * Dd];       // mems @ Wc^T + bc              [1536,512]
__device__ float g_part[ROWS * Dd];      // inputs @ Wout[:,512:]^T + bout[768,512]
__device__ float g_c[ROWS * Dd];         // context                       [768,512]

#define NEG_INF (-__int_as_float(0x7f800000))

__device__ __forceinline__ float tanh_ap(float x) {
    float y;
    asm("tanh.approx.f32 %0, %1;" : "=f"(y) : "f"(x));
    return y;
}
__device__ __forceinline__ unsigned long long ffma2(unsigned long long a,
                                                    unsigned long long b,
                                                    unsigned long long c) {
    unsigned long long d;
    asm("fma.rn.f32x2 %0, %1, %2, %3;" : "=l"(d) : "l"(a), "l"(b), "l"(c));
    return d;
}
__device__ __forceinline__ unsigned long long dup2(float x) {
    unsigned long long d;
    asm("mov.b64 %0, {%1, %1};" : "=l"(d) : "f"(x));
    return d;
}
__device__ __forceinline__ float2 unpk(unsigned long long p) {
    float lo, hi;
    asm("mov.b64 {%0, %1}, %2;" : "=f"(lo), "=f"(hi) : "l"(p));
    return make_float2(lo, hi);
}

// ---------------------------------------------------------------------------
// f32x2-packed GEMM body — EXACTLY the R5-measured version (single-buffered,
// W dup'd via MOV in the inner loop; A LDS.64 loads are warp-broadcast).
// BM=64: 4m x 4n microtile (P=2 m-pairs).  256 threads, BK=16, K=512.
// ---------------------------------------------------------------------------
template <int BM>
__device__ __forceinline__ void gemm_body(
    float (*As)[BM + 4], float (*Ws)[68],
    const float* __restrict__ A, int lda,
    const float* __restrict__ W, int ldw,
    const float* __restrict__ bias,
    const float* __restrict__ part,
    float* __restrict__ C,
    int bm, int bn)
{
    constexpr int MT = BM / 16;    // 4 for BM=64
    constexpr int P  = MT / 2;     // 2

    const int tid = threadIdx.x;
    const int tx = tid & 15;
    const int ty = tid >> 4;
    const int lr = tid >> 2;         // 0..63
    const int lk = (tid & 3) * 4;    // 0,4,8,12

    const float* Ap0 = A + (size_t)(bm + lr) * lda + lk;
    const float* Ap1 = A + (size_t)(bm + lr + 64) * lda + lk;   // BM==128 only
    const float* Wp  = W + (size_t)(bn + lr) * ldw + lk;

    unsigned long long acc[P][4];
#pragma unroll
    for (int p = 0; p < P; p++)
#pragma unroll
        for (int j = 0; j < 4; j++) acc[p][j] = 0ull;

#pragma unroll 1
    for (int k0 = 0; k0 < Dd; k0 += 16) {
        float4 a0 = *reinterpret_cast<const float4*>(Ap0 + k0);
        As[lk + 0][lr] = a0.x; As[lk + 1][lr] = a0.y;
        As[lk + 2][lr] = a0.z; As[lk + 3][lr] = a0.w;
        if (BM == 128) {
            float4 a1 = *reinterpret_cast<const float4*>(Ap1 + k0);
            As[lk + 0][lr + 64] = a1.x; As[lk + 1][lr + 64] = a1.y;
            As[lk + 2][lr + 64] = a1.z; As[lk + 3][lr + 64] = a1.w;
        }
        float4 wv = *reinterpret_cast<const float4*>(Wp + k0);
        Ws[lk + 0][lr] = wv.x; Ws[lk + 1][lr] = wv.y;
        Ws[lk + 2][lr] = wv.z; Ws[lk + 3][lr] = wv.w;
        __syncthreads();

#pragma unroll
        for (int k = 0; k < 16; k++) {
            unsigned long long ap[P];
            const float* ar = &As[k][ty * MT];
#pragma unroll
            for (int p = 0; p < P; p++)
                ap[p] = *reinterpret_cast<const unsigned long long*>(ar + 2 * p);
            float4 w4 = *reinterpret_cast<const float4*>(&Ws[k][tx * 4]);
            unsigned long long wd[4] = {dup2(w4.x), dup2(w4.y), dup2(w4.z), dup2(w4.w)};
#pragma unroll
            for (int p = 0; p < P; p++)
#pragma unroll
                for (int j = 0; j < 4; j++)
                    acc[p][j] = ffma2(ap[p], wd[j], acc[p][j]);
        }
        __syncthreads();
    }

#pragma unroll
    for (int j = 0; j < 4; j++) {
        const int n = bn + tx * 4 + j;
        const float bv = bias ? bias[n] : 0.f;
#pragma unroll
        for (int p = 0; p < P; p++) {
            const int m = bm + ty * MT + 2 * p;
            float2 val = unpk(acc[p][j]);
            float v0 = val.x + bv, v1 = val.y + bv;
            if (part) {
                v0 += part[(size_t)m * Dd + n];
                v1 += part[(size_t)(m + 1) * Dd + n];
            }
            C[(size_t)m * Dd + n] = v0;
            C[(size_t)(m + 1) * Dd + n] = v1;
        }
    }
}

// ---------------------------------------------------------------------------
// Launch 1: three independent GEMMs, now 64x64 tiles (384 blocks, was 192).
//   [0,96):    g_wq   = inputs @ Wq^T                 (12x8 tiles)
//   [96,288):  g_uh   = mems @ Wc^T + bc              (24x8 tiles)
//   [288,384): g_part = inputs @ Wout[:,512:]^T + bout(12x8 tiles)
// ---------------------------------------------------------------------------
__global__ __launch_bounds__(256) void mega_gemm1(
    const float* __restrict__ inputs, const float* __restrict__ mems,
    const float* __restrict__ Wq, const float* __restrict__ Wc,
    const float* __restrict__ bc, const float* __restrict__ Wout,
    const float* __restrict__ bout)
{
    __shared__ float As[16][68];
    __shared__ float Ws[16][68];
    const int bx = blockIdx.x;
    if (bx < 96) {
        gemm_body<64>(As, Ws, inputs, Dd, Wq, Dd, nullptr, nullptr, g_wq,
                      (bx >> 3) * 64, (bx & 7) * 64);
    } else if (bx < 288) {
        const int t = bx - 96;
        gemm_body<64>(As, Ws, mems, Dd, Wc, Dd, bc, nullptr, g_uh,
                      (t >> 3) * 64, (t & 7) * 64);
    } else {
        const int t = bx - 288;
        gemm_body<64>(As, Ws, inputs, Dd, Wout + Dd, 2 * Dd, bout, nullptr, g_part,
                      (t >> 3) * 64, (t & 7) * 64);
    }
}

// Launch 3: attn_h = c @ Wout[:, :512]^T + g_part   (96 blocks, 64x64 tiles)
__global__ __launch_bounds__(256) void gemm2(const float* __restrict__ Wout,
                                             float* __restrict__ out_attn)
{
    __shared__ float As[16][68];
    __shared__ float Ws[16][68];
    gemm_body<64>(As, Ws, g_c, Dd, Wout, 2 * Dd, nullptr, g_part, out_attn,
                  (blockIdx.x >> 3) * 64, (blockIdx.x & 7) * 64);
}

// ---------------------------------------------------------------------------
// Fused: tanh-score -> masked softmax -> align out -> context -> g_c
// One block per (b,t) row — the R5-measured version.  768 blocks.
// ---------------------------------------------------------------------------
__global__ __launch_bounds__(256) void attn_fused(
    const float* __restrict__ mems, const int* __restrict__ mem_masks,
    const float* __restrict__ v, float* __restrict__ out_align)
{
    __shared__ float sm_logit[Ss];
    __shared__ float smw[Ss];
    __shared__ float red[256];

    const int row = blockIdx.x;
    const int b = row / Tt;
    const int tid = threadIdx.x;
    const int warp = tid >> 5;
    const int lane = tid & 31;
    const int len = mem_masks[b];

    const float* wqrow = g_wq + (size_t)row * Dd;
    float4 wqr[4], vr[4];
#pragma unroll
    for (int j = 0; j < 4; j++) {
        wqr[j] = *reinterpret_cast<const float4*>(wqrow + j * 128 + lane * 4);
        vr[j]  = *reinterpret_cast<const float4*>(v + j * 128 + lane * 4);
    }

#pragma unroll 1
    for (int it = 0; it < Ss / 8; it++) {
        const int s = it * 8 + warp;
        if (s < len) {
            const float* uhp = g_uh + (size_t)(b * Ss + s) * Dd;
            float acc = 0.f;
#pragma unroll
            for (int j = 0; j < 4; j++) {
                float4 u = *reinterpret_cast<const float4*>(uhp + j * 128 + lane * 4);
                acc = fmaf(vr[j].x, tanh_ap(wqr[j].x + u.x), acc);
                acc = fmaf(vr[j].y, tanh_ap(wqr[j].y + u.y), acc);
                acc = fmaf(vr[j].z, tanh_ap(wqr[j].z + u.z), acc);
                acc = fmaf(vr[j].w, tanh_ap(wqr[j].w + u.w), acc);
            }
#pragma unroll
            for (int o = 16; o; o >>= 1) acc += __shfl_xor_sync(0xFFFFFFFFu, acc, o);
            if (lane == 0) sm_logit[s] = acc;
        }
    }
    __syncthreads();

    const bool valid = (tid < Ss) && (tid < len);
    float x = valid ? sm_logit[tid] : NEG_INF;
    red[tid] = x;
    __syncthreads();
#pragma unroll
    for (int s = 128; s > 0; s >>= 1) {
        if (tid < s) red[tid] = fmaxf(red[tid], red[tid + s]);
        __syncthreads();
    }
    const float mx = red[0];
    __syncthreads();

    const float e = valid ? __expf(x - mx) : 0.f;
    red[tid] = e;
    __syncthreads();
#pragma unroll
    for (int s = 128; s > 0; s >>= 1) {
        if (tid < s) red[tid] += red[tid + s];
        __syncthreads();
    }
    const float rsum = 1.f / red[0];

    if (tid < Ss) {
        const float w = e * rsum;
        smw[tid] = w;
        out_align[(size_t)row * Ss + tid] = w;
    }
    __syncthreads();

    const int d0 = tid * 2;
    const float* mb = mems + (size_t)b * Ss * Dd + d0;
    float cx = 0.f, cy = 0.f;
#pragma unroll 4
    for (int s = 0; s < Ss; s += 4) {
        float4 w4 = *reinterpret_cast<const float4*>(&smw[s]);
        float2 m0 = *reinterpret_cast<const float2*>(mb + (size_t)(s + 0) * Dd);
        float2 m1 = *reinterpret_cast<const float2*>(mb + (size_t)(s + 1) * Dd);
        float2 m2 = *reinterpret_cast<const float2*>(mb + (size_t)(s + 2) * Dd);
        float2 m3 = *reinterpret_cast<const float2*>(mb + (size_t)(s + 3) * Dd);
        cx = fmaf(w4.x, m0.x, cx); cy = fmaf(w4.x, m0.y, cy);
        cx = fmaf(w4.y, m1.x, cx); cy = fmaf(w4.y, m1.y, cy);
        cx = fmaf(w4.z, m2.x, cx); cy = fmaf(w4.z, m2.y, cy);
        cx = fmaf(w4.w, m3.x, cx); cy = fmaf(w4.w, m3.y, cy);
    }
    float2 c2; c2.x = cx; c2.y = cy;
    *reinterpret_cast<float2*>(g_c + (size_t)row * Dd + d0) = c2;
}

// ---------------------------------------------------------------------------
extern "C" void kernel_launch(void* const* d_in, const int* in_sizes, int n_in,
                              void* d_out, int out_size) {
    const float* inputs    = (const float*)d_in[0];
    const float* mems      = (const float*)d_in[1];
    const int*   mem_masks = (const int*)d_in[2];
    const float* Wq        = (const float*)d_in[3];
    const float* Wc        = (const float*)d_in[4];
    const float* bc        = (const float*)d_in[5];
    const float* v         = (const float*)d_in[6];
    const float* Wout      = (const float*)d_in[7];
    const float* bout      = (const float*)d_in[8];

    float* out_attn  = (float*)d_out;               // [768,512]
    float* out_align = (float*)d_out + ROWS * Dd;   // [768,192]

    mega_gemm1<<<384, 256>>>(inputs, mems, Wq, Wc, bc, Wout, bout);
    attn_fused<<<ROWS, 256>>>(mems, mem_masks, v, out_align);
    gemm2<<<96, 256>>>(Wout, out_attn);
}